// round 6
// baseline (speedup 1.0000x reference)
#include <cuda_runtime.h>
#include <cstdint>

// Problem constants
#define N_VOX   262144       // 8 * 32*32*32 voxels
#define KCODES  256
#define EMB     32
#define SPATIAL 32768        // 32*32*32 voxels per batch
#define CH_STRIDE 32768      // element stride between channels in x / out
#define BATCH_STRIDE 1048576 // 32 channels * 32768
#define OUT_Q_ELEMS 8388608  // 8*32*32768

// ---------------- device-global scratch (allocation-free) ----------------
// Zero at module load; finalize_kernel resets them after each use, so every
// invocation (correctness run and each graph replay) starts from zero.
__device__ double g_commit;
__device__ double g_som;
__device__ unsigned long long g_count;

// ---------------- packed f32x2 helpers ----------------
__device__ __forceinline__ unsigned long long pack2(float lo, float hi) {
    unsigned long long r;
    asm("mov.b64 %0, {%1, %2};" : "=l"(r) : "f"(lo), "f"(hi));
    return r;
}
__device__ __forceinline__ float2 unpack2(unsigned long long v) {
    float lo, hi;
    asm("mov.b64 {%0, %1}, %2;" : "=f"(lo), "=f"(hi) : "l"(v));
    return make_float2(lo, hi);
}
__device__ __forceinline__ unsigned long long fma2(unsigned long long a,
                                                   unsigned long long b,
                                                   unsigned long long c) {
    unsigned long long r;
    asm("fma.rn.f32x2 %0, %1, %2, %3;" : "=l"(r) : "l"(a), "l"(b), "l"(c));
    return r;
}

// Distance from this thread's x (16 packed f32x2 regs) to codebook row j.
// W rows read from global (L1-resident 32KB) — per-lane-divergent j would be a
// 32-way LDS bank conflict against the k-major shared tile, L1 hits are cheaper.
__device__ __forceinline__ float dist_to_row(const float* __restrict__ Wc,
                                             const float* __restrict__ sWsq,
                                             const unsigned long long* xr,
                                             float xsq, int j) {
    const float4* gw = (const float4*)(Wc + j * EMB);
    float dot = 0.f;
#pragma unroll
    for (int i = 0; i < 8; i++) {
        float4 wv = gw[i];
        float2 xa = unpack2(xr[2 * i]);
        float2 xb = unpack2(xr[2 * i + 1]);
        dot += wv.x * xa.x + wv.y * xa.y + wv.z * xb.x + wv.w * xb.y;
    }
    return fmaf(-2.f, dot, xsq + sWsq[j]);
}

// ---------------- fused kernel: distances, argmin, out, enc, losses --------
__global__ __launch_bounds__(256) void som_main_kernel(
    const float* __restrict__ x,
    const float* __restrict__ Wc,
    float* __restrict__ outq,
    float* __restrict__ enc)
{
    __shared__ __align__(16) float sW[KCODES][EMB];  // 32 KB, k-major
    __shared__ float sWsq[KCODES];
    __shared__ int   sBestk[256];
    __shared__ float rc[8], rs[8], rn[8];

    const int t = threadIdx.x;

    // cooperative load of codebook: 2048 float4, 8 per thread
    {
        const float4* Wv  = (const float4*)Wc;
        float4*       sWv = (float4*)&sW[0][0];
#pragma unroll
        for (int i = 0; i < 8; i++)
            sWv[t + 256 * i] = Wv[t + 256 * i];
    }
    __syncthreads();
    {
        float s = 0.f;
#pragma unroll
        for (int c = 0; c < EMB; c++) { float v = sW[t][c]; s += v * v; }
        sWsq[t] = s;
    }
    __syncthreads();

    const int n = blockIdx.x * 256 + t;
    const int b = n >> 15;            // batch
    const int sp = n & (SPATIAL - 1); // spatial offset within batch
    const float* xp = x + (size_t)b * BATCH_STRIDE + sp;

    // load x row into 16 packed f32x2 registers; compute ||x||^2
    unsigned long long xr[16];
    float xsq = 0.f;
#pragma unroll
    for (int c = 0; c < EMB; c += 2) {
        float a0 = xp[(size_t)c * CH_STRIDE];
        float a1 = xp[(size_t)(c + 1) * CH_STRIDE];
        xr[c >> 1] = pack2(a0, a1);
        xsq += a0 * a0 + a1 * a1;
    }

    // ---- distance scan over 256 codes (packed fp32x2 FMAs, broadcast LDS) ----
    float best = 3.402823466e38f;
    int   bestk = 0;
#pragma unroll 2
    for (int k = 0; k < KCODES; k++) {
        const ulonglong2* wr = (const ulonglong2*)sW[k];
        unsigned long long acc0 = 0ull, acc1 = 0ull;
#pragma unroll
        for (int i = 0; i < 8; i++) {
            ulonglong2 wv = wr[i];
            acc0 = fma2(xr[2 * i],     wv.x, acc0);
            acc1 = fma2(xr[2 * i + 1], wv.y, acc1);
        }
        float2 a = unpack2(acc0);
        float2 b2 = unpack2(acc1);
        float dot = (a.x + a.y) + (b2.x + b2.y);
        float dist = fmaf(-2.f, dot, xsq + sWsq[k]);
        if (dist < best) { best = dist; bestk = k; }   // first-min tiebreak
    }

    sBestk[t] = bestk;

    // ---- write quantized output (straight-through == W[bestk]) ----
    {
        float* op = outq + (size_t)b * BATCH_STRIDE + sp;
        const float4* gw = (const float4*)(Wc + bestk * EMB);
#pragma unroll
        for (int i = 0; i < 8; i++) {
            float4 wv = gw[i];
            op[(size_t)(4 * i + 0) * CH_STRIDE] = wv.x;
            op[(size_t)(4 * i + 1) * CH_STRIDE] = wv.y;
            op[(size_t)(4 * i + 2) * CH_STRIDE] = wv.z;
            op[(size_t)(4 * i + 3) * CH_STRIDE] = wv.w;
        }
    }

    // ---- somloss: sum of dist to grid neighbors of bestk (incl. self) ----
    float somv = best;   // self distance == dist[n, bestk]
    int   cnt  = 1;
    const int h = bestk >> 4;
    const int w = bestk & 15;
    if (h > 0)  { somv += dist_to_row(Wc, sWsq, xr, xsq, bestk - 16); cnt++; }
    if (h < 15) { somv += dist_to_row(Wc, sWsq, xr, xsq, bestk + 16); cnt++; }
    if (w > 0)  { somv += dist_to_row(Wc, sWsq, xr, xsq, bestk - 1);  cnt++; }
    if (w < 15) { somv += dist_to_row(Wc, sWsq, xr, xsq, bestk + 1);  cnt++; }

    // commitment per voxel == best distance (||x - W[k*]||^2)
    float cs = best;
    float ss = somv;
    float ns = (float)cnt;

    // ---- block reduction -> double atomics ----
#pragma unroll
    for (int o = 16; o > 0; o >>= 1) {
        cs += __shfl_down_sync(0xffffffffu, cs, o);
        ss += __shfl_down_sync(0xffffffffu, ss, o);
        ns += __shfl_down_sync(0xffffffffu, ns, o);
    }
    const int wid = t >> 5, lid = t & 31;
    if (lid == 0) { rc[wid] = cs; rs[wid] = ss; rn[wid] = ns; }
    __syncthreads();   // covers sBestk[] for the epilogue AND rc/rs/rn for t0
    if (t == 0) {
        float c = 0.f, s2 = 0.f, nn = 0.f;
#pragma unroll
        for (int i = 0; i < 8; i++) { c += rc[i]; s2 += rs[i]; nn += rn[i]; }
        atomicAdd(&g_commit, (double)c);
        atomicAdd(&g_som,    (double)s2);
        atomicAdd(&g_count,  (unsigned long long)(nn + 0.5f));
    }

    // ---- fused one-hot encodings: block writes its own 256x256 tile ----
    // thread = column => 128B contiguous per warp; sBestk[r] is broadcast LDS.
    {
        float* encBlock = enc + (size_t)blockIdx.x * (256 * KCODES);
#pragma unroll 8
        for (int r = 0; r < 256; r++) {
            encBlock[(size_t)r * KCODES + t] = (sBestk[r] == t) ? 1.0f : 0.0f;
        }
    }
}

// ---------------- finalize: loss scalar + accumulator reset ----------------
__global__ void finalize_kernel(float* __restrict__ out0)
{
    const double commitment = g_commit / (double)OUT_Q_ELEMS;  // mean over N*C
    const double som        = g_som / (double)g_count;
    out0[0] = (float)(6.0 * commitment + 1.0 * som);
    // reset for the next invocation (keeps kernel_launch deterministic)
    g_commit = 0.0;
    g_som    = 0.0;
    g_count  = 0ull;
}

// ---------------- launch ----------------
extern "C" void kernel_launch(void* const* d_in, const int* in_sizes, int n_in,
                              void* d_out, int out_size)
{
    const float* x  = (const float*)d_in[0];   // [8,32,32,32,32] f32
    const float* Wc = (const float*)d_in[1];   // [256,32] f32
    float* out = (float*)d_out;

    float* loss_ptr = out;                      // 1 element
    float* outq     = out + 1;                  // 8388608 elements
    float* enc      = out + 1 + OUT_Q_ELEMS;    // 67108864 elements

    som_main_kernel<<<N_VOX / 256, 256>>>(x, Wc, outq, enc);
    finalize_kernel<<<1, 1>>>(loss_ptr);
}

// round 8
// speedup vs baseline: 1.3455x; 1.3455x over previous
#include <cuda_runtime.h>
#include <cstdint>

// Problem constants
#define N_VOX   262144       // 8 * 32*32*32 voxels
#define KCODES  256
#define EMB     32
#define SPATIAL 32768        // 32*32*32 voxels per batch
#define CH_STRIDE 32768
#define BATCH_STRIDE 1048576 // 32 * 32768
#define OUT_Q_ELEMS 8388608  // 8*32*32768
#define SPAD 36              // padded row stride (floats) for neighbor-sum table

// ---------------- device-global scratch (allocation-free) ----------------
// Zero at module load; the finalizing block resets them each run.
__device__ double g_commit;
__device__ double g_som;
__device__ unsigned long long g_count;
__device__ unsigned int g_ticket;

// ---------------- packed f32x2 helpers ----------------
__device__ __forceinline__ unsigned long long pack2(float lo, float hi) {
    unsigned long long r;
    asm("mov.b64 %0, {%1, %2};" : "=l"(r) : "f"(lo), "f"(hi));
    return r;
}
__device__ __forceinline__ float2 unpack2(unsigned long long v) {
    float lo, hi;
    asm("mov.b64 {%0, %1}, %2;" : "=f"(lo), "=f"(hi) : "l"(v));
    return make_float2(lo, hi);
}
__device__ __forceinline__ unsigned long long fma2(unsigned long long a,
                                                   unsigned long long b,
                                                   unsigned long long c) {
    unsigned long long r;
    asm("fma.rn.f32x2 %0, %1, %2, %3;" : "=l"(r) : "l"(a), "l"(b), "l"(c));
    return r;
}
__device__ __forceinline__ unsigned long long add2(unsigned long long a,
                                                   unsigned long long b) {
    unsigned long long r;
    asm("add.rn.f32x2 %0, %1, %2;" : "=l"(r) : "l"(a), "l"(b));
    return r;
}

// ---------------- single fused kernel ----------------
// Dynamic shared layout (bytes):
//   sW    [256*32] f32 : 0      (32768)  codebook, k-major
//   sS    [256*36] f32 : 32768  (36864)  neighbor-summed codebook, padded
//   sWsq  [256]    f32 : 69632  (1024)
//   sSwsq [256]    f32 : 70656  (1024)   sum of ||w||^2 over N(k) incl self
//   sBest [512]    i32 : 71680  (2048)
//   sRed  [24]     f32 : 73728  (96)
#define SMEM_BYTES 73824

__global__ __launch_bounds__(256, 2) void som_main_kernel(
    const float* __restrict__ x,
    const float* __restrict__ Wc,
    float* __restrict__ outq,
    float* __restrict__ enc,
    float* __restrict__ loss_out)
{
    extern __shared__ __align__(16) char dyn[];
    float* sW    = (float*)(dyn);
    float* sS    = (float*)(dyn + 32768);
    float* sWsq  = (float*)(dyn + 69632);
    float* sSwsq = (float*)(dyn + 70656);
    int*   sBest = (int*)  (dyn + 71680);
    float* sRed  = (float*)(dyn + 73728);   // rc[8], rs[8], rn[8]

    const int t = threadIdx.x;

    // ---- prologue 1: coop load codebook + row sq-norms via shuffles ----
    {
        const float4* Wv  = (const float4*)Wc;
        float4*       sWv = (float4*)sW;
#pragma unroll
        for (int i = 0; i < 8; i++) {
            float4 v = Wv[t + 256 * i];
            sWv[t + 256 * i] = v;
            float ps = v.x * v.x + v.y * v.y + v.z * v.z + v.w * v.w;
            // 8 consecutive lanes own one 32-float row
            ps += __shfl_xor_sync(0xffffffffu, ps, 1);
            ps += __shfl_xor_sync(0xffffffffu, ps, 2);
            ps += __shfl_xor_sync(0xffffffffu, ps, 4);
            if ((t & 7) == 0) sWsq[(t + 256 * i) >> 3] = ps;
        }
    }
    __syncthreads();

    // ---- prologue 2: neighbor-sum table, column-parallel (conflict-free) ----
    {
#pragma unroll 4
        for (int i = 0; i < 32; i++) {
            const int k = (t >> 5) + 8 * i;     // uniform per warp
            const int c = t & 31;               // lane = column
            float s = sW[k * 32 + c];
            if (k >= 16)        s += sW[(k - 16) * 32 + c];
            if (k < 240)        s += sW[(k + 16) * 32 + c];
            if ((k & 15) != 0)  s += sW[(k - 1) * 32 + c];
            if ((k & 15) != 15) s += sW[(k + 1) * 32 + c];
            sS[k * SPAD + c] = s;
            if (c == 0) {
                float q = sWsq[k];
                if (k >= 16)        q += sWsq[k - 16];
                if (k < 240)        q += sWsq[k + 16];
                if ((k & 15) != 0)  q += sWsq[k - 1];
                if ((k & 15) != 15) q += sWsq[k + 1];
                sSwsq[k] = q;
            }
        }
    }
    __syncthreads();

    // ---- load two x rows (voxels A = base, B = base+256) ----
    const int base = blockIdx.x * 512 + t;      // block covers 512 voxels, same batch
    const int b  = base >> 15;
    const int sp = base & (SPATIAL - 1);
    const float* xpA = x + (size_t)b * BATCH_STRIDE + sp;
    const float* xpB = xpA + 256;

    unsigned long long xrA[16], xrB[16];
    float xsqA = 0.f, xsqB = 0.f;
#pragma unroll
    for (int c = 0; c < EMB; c += 2) {
        float a0 = xpA[(size_t)c * CH_STRIDE];
        float b0 = xpB[(size_t)c * CH_STRIDE];
        float a1 = xpA[(size_t)(c + 1) * CH_STRIDE];
        float b1 = xpB[(size_t)(c + 1) * CH_STRIDE];
        xrA[c >> 1] = pack2(a0, a1);
        xrB[c >> 1] = pack2(b0, b1);
        xsqA += a0 * a0 + a1 * a1;
        xsqB += b0 * b0 + b1 * b1;
    }

    // ---- distance scan: 256 codes, 2 voxels per thread ----
    float bestA = 3.402823466e38f, bestB = 3.402823466e38f;
    int   bkA = 0, bkB = 0;
#pragma unroll 2
    for (int k = 0; k < KCODES; k++) {
        const ulonglong2* wr = (const ulonglong2*)(sW + k * 32);
        unsigned long long a0 = 0ull, a1 = 0ull, c0 = 0ull, c1 = 0ull;
#pragma unroll
        for (int i = 0; i < 8; i++) {
            ulonglong2 wv = wr[i];
            a0 = fma2(xrA[2 * i],     wv.x, a0);
            a1 = fma2(xrA[2 * i + 1], wv.y, a1);
            c0 = fma2(xrB[2 * i],     wv.x, c0);
            c1 = fma2(xrB[2 * i + 1], wv.y, c1);
        }
        const float wsq = sWsq[k];
        {
            float2 s = unpack2(add2(a0, a1));
            float dist = fmaf(-2.f, s.x + s.y, xsqA + wsq);
            if (dist < bestA) { bestA = dist; bkA = k; }
        }
        {
            float2 s = unpack2(add2(c0, c1));
            float dist = fmaf(-2.f, s.x + s.y, xsqB + wsq);
            if (dist < bestB) { bestB = dist; bkB = k; }
        }
    }

    sBest[t]       = bkA;
    sBest[t + 256] = bkB;

    // ---- quantized outputs (straight-through == W[bestk]) ----
    {
        float* opA = outq + (size_t)b * BATCH_STRIDE + sp;
        float* opB = opA + 256;
        const float4* gwA = (const float4*)(Wc + bkA * EMB);
        const float4* gwB = (const float4*)(Wc + bkB * EMB);
#pragma unroll
        for (int i = 0; i < 8; i++) {
            float4 va = gwA[i];
            float4 vb = gwB[i];
            opA[(size_t)(4 * i + 0) * CH_STRIDE] = va.x;
            opA[(size_t)(4 * i + 1) * CH_STRIDE] = va.y;
            opA[(size_t)(4 * i + 2) * CH_STRIDE] = va.z;
            opA[(size_t)(4 * i + 3) * CH_STRIDE] = va.w;
            opB[(size_t)(4 * i + 0) * CH_STRIDE] = vb.x;
            opB[(size_t)(4 * i + 1) * CH_STRIDE] = vb.y;
            opB[(size_t)(4 * i + 2) * CH_STRIDE] = vb.z;
            opB[(size_t)(4 * i + 3) * CH_STRIDE] = vb.w;
        }
    }

    // ---- somloss via neighbor-aggregate:  cnt*xsq + sum(wsq) - 2*x.S[k*] ----
    float somA, somB;
    int cntA, cntB;
    {
        const ulonglong2* sr = (const ulonglong2*)(sS + bkA * SPAD);
        unsigned long long d0 = 0ull, d1 = 0ull;
#pragma unroll
        for (int i = 0; i < 8; i++) {
            ulonglong2 wv = sr[i];
            d0 = fma2(xrA[2 * i],     wv.x, d0);
            d1 = fma2(xrA[2 * i + 1], wv.y, d1);
        }
        float2 s = unpack2(add2(d0, d1));
        cntA = 1 + (bkA >= 16) + (bkA < 240) + ((bkA & 15) != 0) + ((bkA & 15) != 15);
        somA = fmaf(-2.f, s.x + s.y, fmaf((float)cntA, xsqA, sSwsq[bkA]));
    }
    {
        const ulonglong2* sr = (const ulonglong2*)(sS + bkB * SPAD);
        unsigned long long d0 = 0ull, d1 = 0ull;
#pragma unroll
        for (int i = 0; i < 8; i++) {
            ulonglong2 wv = sr[i];
            d0 = fma2(xrB[2 * i],     wv.x, d0);
            d1 = fma2(xrB[2 * i + 1], wv.y, d1);
        }
        float2 s = unpack2(add2(d0, d1));
        cntB = 1 + (bkB >= 16) + (bkB < 240) + ((bkB & 15) != 0) + ((bkB & 15) != 15);
        somB = fmaf(-2.f, s.x + s.y, fmaf((float)cntB, xsqB, sSwsq[bkB]));
    }

    // ---- block reduction -> double atomics ----
    float cs = bestA + bestB;        // commitment = best distances exactly
    float ss = somA + somB;
    float ns = (float)(cntA + cntB);
#pragma unroll
    for (int o = 16; o > 0; o >>= 1) {
        cs += __shfl_down_sync(0xffffffffu, cs, o);
        ss += __shfl_down_sync(0xffffffffu, ss, o);
        ns += __shfl_down_sync(0xffffffffu, ns, o);
    }
    const int wid = t >> 5, lid = t & 31;
    if (lid == 0) { sRed[wid] = cs; sRed[8 + wid] = ss; sRed[16 + wid] = ns; }
    __syncthreads();   // covers sBest for enc epilogue AND sRed for t0
    if (t == 0) {
        float c = 0.f, s2 = 0.f, nn = 0.f;
#pragma unroll
        for (int i = 0; i < 8; i++) { c += sRed[i]; s2 += sRed[8 + i]; nn += sRed[16 + i]; }
        atomicAdd(&g_commit, (double)c);
        atomicAdd(&g_som,    (double)s2);
        atomicAdd(&g_count,  (unsigned long long)(nn + 0.5f));
    }

    // ---- one-hot encodings: block's own 512x256 tile, coalesced ----
    {
        float* encBlock = enc + (size_t)blockIdx.x * (512 * KCODES);
#pragma unroll 8
        for (int r = 0; r < 512; r++) {
            encBlock[(size_t)r * KCODES + t] = (sBest[r] == t) ? 1.0f : 0.0f;
        }
    }

    // ---- last block computes the loss scalar and resets accumulators ----
    __threadfence();
    __shared__ unsigned int sLast;
    if (t == 0) sLast = atomicAdd(&g_ticket, 1u);
    __syncthreads();
    if (sLast == gridDim.x - 1 && t == 0) {
        double c = atomicAdd(&g_commit, 0.0);
        double s = atomicAdd(&g_som, 0.0);
        unsigned long long n = atomicAdd(&g_count, 0ull);
        loss_out[0] = (float)(6.0 * (c / (double)OUT_Q_ELEMS) + s / (double)n);
        g_commit = 0.0;
        g_som    = 0.0;
        g_count  = 0ull;
        __threadfence();
        atomicExch(&g_ticket, 0u);
    }
}

// ---------------- launch ----------------
extern "C" void kernel_launch(void* const* d_in, const int* in_sizes, int n_in,
                              void* d_out, int out_size)
{
    const float* x  = (const float*)d_in[0];   // [8,32,32,32,32] f32
    const float* Wc = (const float*)d_in[1];   // [256,32] f32
    float* out = (float*)d_out;

    float* loss_ptr = out;                      // 1 element
    float* outq     = out + 1;                  // 8388608 elements
    float* enc      = out + 1 + OUT_Q_ELEMS;    // 67108864 elements

    cudaFuncSetAttribute(som_main_kernel,
                         cudaFuncAttributeMaxDynamicSharedMemorySize, SMEM_BYTES);
    som_main_kernel<<<N_VOX / 512, 256, SMEM_BYTES>>>(x, Wc, outq, enc, loss_ptr);
}